// round 6
// baseline (speedup 1.0000x reference)
#include <cuda_runtime.h>
#include <math.h>

#define BATCH  8
#define NPTS   131072
#define DIM    32
#define NLAB   33
#define KINST  32
#define CHUNK  512
#define CHUNKS (NPTS / CHUNK)        // 256 chunks (and blocks) per batch per pass
#define THREADS 256
#define NWARP   8
#define WPTS    (CHUNK / NWARP)      // 64 points per warp
#define P1BLOCKS (BATCH * CHUNKS)    // 2048
#define P3BLOCKS (BATCH * CHUNKS)    // 2048
#define GRID     (P1BLOCKS + P3BLOCKS)
#define ROWW     (KINST + 1)         // padded row width for final matrix

// ---- scratch (no allocations; zeroed by previous replay's final tail) ----
__device__ float g_sums[BATCH * NLAB * DIM];
__device__ float g_counts[BATCH * NLAB];
__device__ float g_hinge[BATCH * NLAB];
__device__ unsigned g_p1done[BATCH];   // monotonic: pass1 block completions per batch
__device__ unsigned g_p3tick[BATCH];   // monotonic: pass3 block start tickets per batch
__device__ unsigned g_fin;             // monotonic: pass3 block completions (global)

__global__ void __launch_bounds__(THREADS) k_fused(const float* __restrict__ emb,
                                                   const int* __restrict__ lab,
                                                   float* __restrict__ out) {
    // union: pass1 sums(8448)+cnt(264) | pass3 mean(1056)+hinge(1056) | final 8448+res
    __shared__ __align__(16) float s_buf[8448 + 264 + 32];
    __shared__ unsigned s_last;
    int tid = threadIdx.x, wid = tid >> 5, lane = tid & 31;

    if (blockIdx.x < P1BLOCKS) {
        // ================= PASS 1: per-(b,label) sums + counts =================
        int b = blockIdx.x / CHUNKS;
        int chunk = blockIdx.x % CHUNKS;
        float (*s_sums)[NLAB * DIM] = (float (*)[NLAB * DIM])s_buf;
        float (*s_cnt)[NLAB]        = (float (*)[NLAB])(s_buf + NWARP * NLAB * DIM);

        for (int i = tid; i < NWARP * NLAB * DIM; i += THREADS) (&s_sums[0][0])[i] = 0.f;
        for (int i = tid; i < NWARP * NLAB; i += THREADS)       (&s_cnt[0][0])[i]  = 0.f;
        __syncthreads();

        const float* ebase = emb + ((size_t)b * NPTS + (size_t)chunk * CHUNK) * DIM;
        const int*   lbase = lab + (size_t)b * NPTS + (size_t)chunk * CHUNK;
        float* ws = s_sums[wid];
        float* wc = s_cnt[wid];
        int p0 = wid * WPTS;

        for (int w = 0; w < WPTS; w += 32) {
            int myl = lbase[p0 + w + lane];                 // coalesced labels
            unsigned peers = __match_any_sync(0xffffffffu, myl);
            if ((__ffs(peers) - 1) == lane)                 // one leader per label
                wc[myl] += (float)__popc(peers);            // distinct addrs: no race
            #pragma unroll
            for (int h = 0; h < 32; h += 16) {
                float v[16];
                #pragma unroll
                for (int i = 0; i < 16; i++)                // 16 LDGs in flight
                    v[i] = ebase[(size_t)(p0 + w + h + i) * DIM + lane];
                #pragma unroll
                for (int i = 0; i < 16; i++) {
                    int l = __shfl_sync(0xffffffffu, myl, h + i);
                    ws[l * DIM + lane] += v[i];             // lane-private: no race
                }
            }
        }
        __syncthreads();

        for (int i = tid; i < NLAB * DIM; i += THREADS) {
            float s = 0.f;
            #pragma unroll
            for (int w = 0; w < NWARP; w++) s += s_sums[w][i];
            atomicAdd(&g_sums[b * NLAB * DIM + i], s);
        }
        for (int i = tid; i < NLAB; i += THREADS) {
            float s = 0.f;
            #pragma unroll
            for (int w = 0; w < NWARP; w++) s += s_cnt[w][i];
            atomicAdd(&g_counts[b * NLAB + i], s);
        }
        // release: this block's contribution is visible, then signal
        __threadfence();
        __syncthreads();
        if (tid == 0) atomicAdd(&g_p1done[b], 1u);
        return;
    }

    // ================= PASS 3: hinge(||x - mean[label]|| - 0.1) =================
    int idx = blockIdx.x - P1BLOCKS;
    int b = idx / CHUNKS;
    int chunk = idx % CHUNKS;

    // gate: wait until this replay's pass1(b) is fully done (monotonic epochs)
    if (tid == 0) {
        unsigned e = atomicAdd(&g_p3tick[b], 1u) >> 8;      // 256 p3 blocks/batch/replay
        unsigned need = (e + 1u) << 8;                      // (epoch+1)*256
        while (atomicAdd(&g_p1done[b], 0u) < need) __nanosleep(64);
    }
    __syncthreads();

    float* s_mean = s_buf;                                  // 1056 floats
    float (*s_h)[NLAB] = (float (*)[NLAB])(s_buf + NLAB * DIM);  // 32 x 33
    int g = lane >> 3, s = lane & 7;

    for (int i = tid; i < NLAB * DIM; i += THREADS) {
        float c = g_counts[b * NLAB + i / DIM];
        s_mean[i] = g_sums[b * NLAB * DIM + i] / fmaxf(c, 1.f);
    }
    for (int i = tid; i < NWARP * 4 * NLAB; i += THREADS) (&s_h[0][0])[i] = 0.f;
    __syncthreads();

    const float4* e4 = (const float4*)(emb + ((size_t)b * NPTS + (size_t)chunk * CHUNK) * DIM);
    const int*    lbase = lab + (size_t)b * NPTS + (size_t)chunk * CHUNK;
    const float4* m4 = (const float4*)s_mean;
    float* wh = s_h[wid * 4 + g];
    int p0 = wid * WPTS;

    for (int w = 0; w < WPTS; w += 32) {
        int myl = lbase[p0 + w + lane];
        float4 v[8]; int lq[8];
        #pragma unroll
        for (int q = 0; q < 8; q++) {                       // 8 LDG.128 in flight
            int p = p0 + w + q * 4 + g;
            v[q] = e4[(size_t)p * 8 + s];                   // 512B/warp contiguous
            lq[q] = __shfl_sync(0xffffffffu, myl, w % 32 + q * 4 + g);
        }
        #pragma unroll
        for (int q = 0; q < 8; q++) {
            float4 m = m4[lq[q] * 8 + s];
            float dx = v[q].x - m.x, dy = v[q].y - m.y;
            float dz = v[q].z - m.z, dw = v[q].w - m.w;
            float sq = dx * dx + dy * dy + dz * dz + dw * dw;
            sq += __shfl_xor_sync(0xffffffffu, sq, 1);
            sq += __shfl_xor_sync(0xffffffffu, sq, 2);
            sq += __shfl_xor_sync(0xffffffffu, sq, 4);
            if (s == 0) {
                float dist = sqrtf(sq + 1e-24f);
                wh[lq[q]] += fmaxf(dist - 0.1f, 0.f);       // group-private
            }
        }
    }
    __syncthreads();

    for (int i = tid; i < NLAB; i += THREADS) {
        float acc = 0.f;
        #pragma unroll
        for (int r = 0; r < NWARP * 4; r++) acc += s_h[r][i];
        atomicAdd(&g_hinge[b * NLAB + i], acc);
    }

    // completion ticket; last pass3 block of this replay runs the finalize
    __threadfence();
    __syncthreads();
    if (tid == 0) {
        unsigned t = atomicAdd(&g_fin, 1u);
        s_last = ((t & (P3BLOCKS - 1u)) == (P3BLOCKS - 1u)) ? 1u : 0u;
    }
    __syncthreads();
    if (!s_last) return;
    __threadfence();

    // ================= FINALIZE (one block; warp = batch) =================
    {
        int b2 = wid;
        float* sm = s_buf + b2 * (DIM * ROWW);              // [d][k] rows of 33
        float* s_res = s_buf + BATCH * DIM * ROWW;          // 16 floats

        float cvec = g_counts[b2 * NLAB + 1 + lane];        // lane <-> label lane+1
        float pres = (cvec > 0.f) ? 1.f : 0.f;
        float hs   = g_hinge[b2 * NLAB + 1 + lane];

        #pragma unroll
        for (int k = 0; k < KINST; k++) {
            float c = __shfl_sync(0xffffffffu, cvec, k);
            sm[lane * ROWW + k] =
                g_sums[b2 * NLAB * DIM + (k + 1) * DIM + lane] / fmaxf(c, 1.f);
        }
        __syncwarp();

        float nrm = 0.f;                                    // lane = instance k
        #pragma unroll
        for (int d = 0; d < DIM; d++) { float x = sm[d * ROWW + lane]; nrm += x * x; }
        float rinv = 1.f / fmaxf(sqrtf(nrm), 1e-12f);

        float mc[DIM];                                      // own normalized column
        #pragma unroll
        for (int d = 0; d < DIM; d++) mc[d] = sm[d * ROWW + lane] * rinv;
        #pragma unroll
        for (int d = 0; d < DIM; d++) sm[d * ROWW + lane] = mc[d];
        __syncwarp();

        float hp = 0.f, pm = 0.f;
        #pragma unroll 4
        for (int i = 0; i < KINST; i++) {
            float pi = __shfl_sync(0xffffffffu, pres, i);
            float mask = (lane > i) ? pi * pres : 0.f;
            float sq = 0.f;
            #pragma unroll
            for (int d = 0; d < DIM; d++) {
                float diff = sm[d * ROWW + i] - mc[d];      // broadcast + register
                sq += diff * diff;
            }
            hp += fmaxf(1.0f - sqrtf(sq + 1e-24f), 0.f) * mask;  // 2*DELTA_D = 1
            pm += mask;
        }

        float seg = hs / fmaxf(cvec, 1.f);
        float segsum = seg, ninst = pres;
        #pragma unroll
        for (int o = 16; o; o >>= 1) {
            segsum += __shfl_xor_sync(0xffffffffu, segsum, o);
            ninst  += __shfl_xor_sync(0xffffffffu, ninst, o);
            hp     += __shfl_xor_sync(0xffffffffu, hp, o);
            pm     += __shfl_xor_sync(0xffffffffu, pm, o);
        }
        if (lane == 0) {
            s_res[b2 * 2]     = segsum / (ninst + 1e-6f);
            s_res[b2 * 2 + 1] = (ninst > 1.f) ? hp / (pm + 1e-6f) : 0.f;
        }
        __syncthreads();

        if (tid < 32) {
            float pull = (lane < BATCH) ? s_res[lane * 2]     : 0.f;
            float push = (lane < BATCH) ? s_res[lane * 2 + 1] : 0.f;
            #pragma unroll
            for (int o = 4; o; o >>= 1) {
                pull += __shfl_xor_sync(0xffffffffu, pull, o);
                push += __shfl_xor_sync(0xffffffffu, push, o);
            }
            if (lane == 0) {
                pull *= (1.0f / BATCH);
                push *= (1.0f / BATCH);
                out[0] = pull + push;
                out[1] = pull;
                out[2] = push;
            }
        }
        __syncthreads();

        // re-zero accumulators for the next replay (out already written)
        for (int i = tid; i < BATCH * NLAB * DIM; i += THREADS) g_sums[i] = 0.f;
        for (int i = tid; i < BATCH * NLAB; i += THREADS) {
            g_counts[i] = 0.f;
            g_hinge[i]  = 0.f;
        }
    }
}

extern "C" void kernel_launch(void* const* d_in, const int* in_sizes, int n_in,
                              void* d_out, int out_size) {
    const float* emb = (const float*)d_in[0];
    const int*   lab = (const int*)d_in[1];
    float* out = (float*)d_out;
    (void)in_sizes; (void)n_in; (void)out_size;

    k_fused<<<GRID, THREADS>>>(emb, lab, out);
}

// round 7
// speedup vs baseline: 1.0866x; 1.0866x over previous
#include <cuda_runtime.h>
#include <math.h>

#define BATCH  8
#define NPTS   131072
#define DIM    32
#define NLAB   33
#define KINST  32
#define CHUNK  512
#define CHUNKS (NPTS / CHUNK)        // 256 chunks per batch
#define NBLK   (BATCH * CHUNKS)      // 2048
#define THREADS 256
#define NWARP   8
#define WPTS    (CHUNK / NWARP)      // 64 points per warp
#define ROWW   (KINST + 1)           // padded row width in finalize

// ---- scratch (no allocations). Zero at module load; k_final re-zeros
// ---- at the end of every run, so each graph replay starts clean.
__device__ float g_sums[BATCH * NLAB * DIM];
__device__ float g_counts[BATCH * NLAB];
__device__ float g_hinge[BATCH * NLAB];

// Pass 1: per-(b,label) sums + counts. Warp-per-point lane-private SMEM RMW
// (race-free); 16 LDGs staged in flight; counts via match_any histogram.
__global__ void __launch_bounds__(THREADS) k_pass1(const float* __restrict__ emb,
                                                   const int* __restrict__ lab) {
    __shared__ float s_sums[NWARP][NLAB * DIM];
    __shared__ float s_cnt[NWARP][NLAB];
    int tid = threadIdx.x, wid = tid >> 5, lane = tid & 31;

    for (int i = tid; i < NWARP * NLAB * DIM; i += THREADS) (&s_sums[0][0])[i] = 0.f;
    for (int i = tid; i < NWARP * NLAB; i += THREADS)       (&s_cnt[0][0])[i]  = 0.f;
    __syncthreads();

    int b = blockIdx.x / CHUNKS;
    int chunk = blockIdx.x % CHUNKS;
    const float* ebase = emb + ((size_t)b * NPTS + (size_t)chunk * CHUNK) * DIM;
    const int*   lbase = lab + (size_t)b * NPTS + (size_t)chunk * CHUNK;

    float* ws = s_sums[wid];
    float* wc = s_cnt[wid];
    int p0 = wid * WPTS;

    for (int w = 0; w < WPTS; w += 32) {
        int myl = lbase[p0 + w + lane];                 // coalesced labels
        unsigned peers = __match_any_sync(0xffffffffu, myl);
        if ((__ffs(peers) - 1) == lane)                 // one leader per label
            wc[myl] += (float)__popc(peers);            // distinct addrs: no race
        #pragma unroll
        for (int h = 0; h < 32; h += 16) {
            float v[16];
            #pragma unroll
            for (int i = 0; i < 16; i++)                // 16 LDGs in flight
                v[i] = ebase[(size_t)(p0 + w + h + i) * DIM + lane];
            #pragma unroll
            for (int i = 0; i < 16; i++) {
                int l = __shfl_sync(0xffffffffu, myl, h + i);
                ws[l * DIM + lane] += v[i];             // lane-private: no race
            }
        }
    }
    __syncthreads();

    for (int i = tid; i < NLAB * DIM; i += THREADS) {
        float s = 0.f;
        #pragma unroll
        for (int w = 0; w < NWARP; w++) s += s_sums[w][i];
        atomicAdd(&g_sums[b * NLAB * DIM + i], s);
    }
    for (int i = tid; i < NLAB; i += THREADS) {
        float s = 0.f;
        #pragma unroll
        for (int w = 0; w < NWARP; w++) s += s_cnt[w][i];
        atomicAdd(&g_counts[b * NLAB + i], s);
    }
}

// Pass 3: hinge(||x - mean[label]|| - 0.1), segment-summed per (b,label).
// float4 quartets: 8 lanes/point, 8 LDG.128 staged, 3-deep shfl reduce,
// group-private hinge replicas (no races).
__global__ void __launch_bounds__(THREADS) k_pass3(const float* __restrict__ emb,
                                                   const int* __restrict__ lab) {
    __shared__ __align__(16) float s_mean[NLAB * DIM];
    __shared__ float s_h[NWARP * 4][NLAB];
    int tid = threadIdx.x, wid = tid >> 5, lane = tid & 31;
    int g = lane >> 3, s = lane & 7;
    int b = blockIdx.x / CHUNKS;
    int chunk = blockIdx.x % CHUNKS;

    for (int i = tid; i < NLAB * DIM; i += THREADS) {
        float c = g_counts[b * NLAB + i / DIM];
        s_mean[i] = g_sums[b * NLAB * DIM + i] / fmaxf(c, 1.f);
    }
    for (int i = tid; i < NWARP * 4 * NLAB; i += THREADS) (&s_h[0][0])[i] = 0.f;
    __syncthreads();

    const float4* e4 = (const float4*)(emb + ((size_t)b * NPTS + (size_t)chunk * CHUNK) * DIM);
    const int*    lbase = lab + (size_t)b * NPTS + (size_t)chunk * CHUNK;
    const float4* m4 = (const float4*)s_mean;
    float* wh = s_h[wid * 4 + g];
    int p0 = wid * WPTS;

    for (int w = 0; w < WPTS; w += 32) {
        int myl = lbase[p0 + w + lane];
        float4 v[8]; int lq[8];
        #pragma unroll
        for (int q = 0; q < 8; q++) {                   // 8 LDG.128 in flight
            int p = p0 + w + q * 4 + g;
            v[q] = e4[(size_t)p * 8 + s];               // 512B/warp contiguous
            lq[q] = __shfl_sync(0xffffffffu, myl, q * 4 + g);
        }
        #pragma unroll
        for (int q = 0; q < 8; q++) {
            float4 m = m4[lq[q] * 8 + s];
            float dx = v[q].x - m.x, dy = v[q].y - m.y;
            float dz = v[q].z - m.z, dw = v[q].w - m.w;
            float sq = dx * dx + dy * dy + dz * dz + dw * dw;
            sq += __shfl_xor_sync(0xffffffffu, sq, 1);
            sq += __shfl_xor_sync(0xffffffffu, sq, 2);
            sq += __shfl_xor_sync(0xffffffffu, sq, 4);
            if (s == 0) {
                float dist = sqrtf(sq + 1e-24f);
                wh[lq[q]] += fmaxf(dist - 0.1f, 0.f);   // group-private
            }
        }
    }
    __syncthreads();

    for (int i = tid; i < NLAB; i += THREADS) {
        float acc = 0.f;
        #pragma unroll
        for (int r = 0; r < NWARP * 4; r++) acc += s_h[r][i];
        atomicAdd(&g_hinge[b * NLAB + i], acc);
    }
}

// Finalize: ONE block, warp w = batch w. Chain-free: per-lane serial norm via
// padded SMEM transpose; single 4-value shfl reduce. Re-zeros accumulators
// at the end so the next graph replay starts clean.
__global__ void __launch_bounds__(THREADS) k_final(float* __restrict__ out) {
    __shared__ __align__(16) float s_buf[BATCH * DIM * ROWW + 16];
    int tid = threadIdx.x, wid = tid >> 5, lane = tid & 31;
    int b = wid;
    float* sm = s_buf + b * (DIM * ROWW);               // [dim][k] rows of 33
    float* s_res = s_buf + BATCH * DIM * ROWW;          // 16 floats

    float cvec = g_counts[b * NLAB + 1 + lane];         // lane <-> label lane+1
    float pres = (cvec > 0.f) ? 1.f : 0.f;
    float hs   = g_hinge[b * NLAB + 1 + lane];

    // means: lane = dim, k = instance
    #pragma unroll
    for (int k = 0; k < KINST; k++) {
        float c = __shfl_sync(0xffffffffu, cvec, k);
        sm[lane * ROWW + k] =
            g_sums[b * NLAB * DIM + (k + 1) * DIM + lane] / fmaxf(c, 1.f);
    }
    __syncwarp();

    // per-lane serial norm (lane = instance k); stride-33 reads: conflict-free
    float nrm = 0.f;
    #pragma unroll
    for (int d = 0; d < DIM; d++) { float x = sm[d * ROWW + lane]; nrm += x * x; }
    float rinv = 1.f / fmaxf(sqrtf(nrm), 1e-12f);

    float mc[DIM];                                      // own normalized column
    #pragma unroll
    for (int d = 0; d < DIM; d++) mc[d] = sm[d * ROWW + lane] * rinv;
    __syncwarp();
    #pragma unroll
    for (int d = 0; d < DIM; d++) sm[d * ROWW + lane] = mc[d];
    __syncwarp();

    float hp = 0.f, pm = 0.f;
    #pragma unroll 4
    for (int i = 0; i < KINST; i++) {
        float pi = __shfl_sync(0xffffffffu, pres, i);
        float mask = (lane > i) ? pi * pres : 0.f;
        float sq = 0.f;
        #pragma unroll
        for (int d = 0; d < DIM; d++) {
            float diff = sm[d * ROWW + i] - mc[d];      // broadcast + register
            sq += diff * diff;
        }
        hp += fmaxf(1.0f - sqrtf(sq + 1e-24f), 0.f) * mask;  // 2*DELTA_D = 1
        pm += mask;
    }

    float seg = hs / fmaxf(cvec, 1.f);
    float segsum = seg, ninst = pres;
    #pragma unroll
    for (int o = 16; o; o >>= 1) {                      // one interleaved reduce
        segsum += __shfl_xor_sync(0xffffffffu, segsum, o);
        ninst  += __shfl_xor_sync(0xffffffffu, ninst, o);
        hp     += __shfl_xor_sync(0xffffffffu, hp, o);
        pm     += __shfl_xor_sync(0xffffffffu, pm, o);
    }
    if (lane == 0) {
        s_res[b * 2]     = segsum / (ninst + 1e-6f);
        s_res[b * 2 + 1] = (ninst > 1.f) ? hp / (pm + 1e-6f) : 0.f;
    }
    __syncthreads();

    if (tid < 32) {
        float pull = (lane < BATCH) ? s_res[lane * 2]     : 0.f;
        float push = (lane < BATCH) ? s_res[lane * 2 + 1] : 0.f;
        #pragma unroll
        for (int o = 4; o; o >>= 1) {
            pull += __shfl_xor_sync(0xffffffffu, pull, o);
            push += __shfl_xor_sync(0xffffffffu, push, o);
        }
        if (lane == 0) {
            pull *= (1.0f / BATCH);
            push *= (1.0f / BATCH);
            out[0] = pull + push;
            out[1] = pull;
            out[2] = push;
        }
    }
    __syncthreads();

    // re-zero accumulators for the next replay (out already written)
    for (int i = tid; i < BATCH * NLAB * DIM; i += THREADS) g_sums[i] = 0.f;
    for (int i = tid; i < BATCH * NLAB; i += THREADS) {
        g_counts[i] = 0.f;
        g_hinge[i]  = 0.f;
    }
}

extern "C" void kernel_launch(void* const* d_in, const int* in_sizes, int n_in,
                              void* d_out, int out_size) {
    const float* emb = (const float*)d_in[0];
    const int*   lab = (const int*)d_in[1];
    float* out = (float*)d_out;
    (void)in_sizes; (void)n_in; (void)out_size;

    k_pass1<<<NBLK, THREADS>>>(emb, lab);
    k_pass3<<<NBLK, THREADS>>>(emb, lab);
    k_final<<<1, THREADS>>>(out);
}

// round 8
// speedup vs baseline: 1.1352x; 1.0447x over previous
#include <cuda_runtime.h>
#include <math.h>

#define BATCH  8
#define NPTS   131072
#define DIM    32
#define NLAB   33
#define KINST  32
#define CHUNK  512
#define CHUNKS (NPTS / CHUNK)        // 256 chunks per batch
#define NBLK   (BATCH * CHUNKS)      // 2048
#define THREADS 256
#define NWARP   8
#define WPTS    (CHUNK / NWARP)      // 64 points per warp
#define ROWW   (KINST + 1)           // padded row width in finalize

// ---- scratch (no allocations). Zero at module load; k_final re-zeros
// ---- at the end of every run, so each graph replay starts clean.
__device__ float g_sums[BATCH * NLAB * DIM];
__device__ float g_counts[BATCH * NLAB];
__device__ float g_hinge[BATCH * NLAB];

// Pass 1: per-(b,label) sums + counts. Warp-per-point lane-private SMEM RMW
// (race-free); 8 LDGs staged (fits in regs -> real MLP); match_any counts.
// Forward order: next replay reads head-first after reversed pass3.
__global__ void __launch_bounds__(THREADS) k_pass1(const float* __restrict__ emb,
                                                   const int* __restrict__ lab) {
    __shared__ float s_sums[NWARP][NLAB * DIM];
    __shared__ float s_cnt[NWARP][NLAB];
    int tid = threadIdx.x, wid = tid >> 5, lane = tid & 31;

    for (int i = tid; i < NWARP * NLAB * DIM; i += THREADS) (&s_sums[0][0])[i] = 0.f;
    for (int i = tid; i < NWARP * NLAB; i += THREADS)       (&s_cnt[0][0])[i]  = 0.f;
    __syncthreads();

    int b = blockIdx.x / CHUNKS;
    int chunk = blockIdx.x % CHUNKS;
    const float* ebase = emb + ((size_t)b * NPTS + (size_t)chunk * CHUNK) * DIM;
    const int*   lbase = lab + (size_t)b * NPTS + (size_t)chunk * CHUNK;

    float* ws = s_sums[wid];
    float* wc = s_cnt[wid];
    int p0 = wid * WPTS;

    for (int w = 0; w < WPTS; w += 32) {
        int myl = lbase[p0 + w + lane];                 // coalesced labels
        unsigned peers = __match_any_sync(0xffffffffu, myl);
        if ((__ffs(peers) - 1) == lane)                 // one leader per label
            wc[myl] += (float)__popc(peers);            // distinct addrs: no race
        #pragma unroll
        for (int h = 0; h < 32; h += 8) {
            float v[8];
            #pragma unroll
            for (int i = 0; i < 8; i++)                 // 8 LDGs genuinely in flight
                v[i] = ebase[(size_t)(p0 + w + h + i) * DIM + lane];
            #pragma unroll
            for (int i = 0; i < 8; i++) {
                int l = __shfl_sync(0xffffffffu, myl, h + i);
                ws[l * DIM + lane] += v[i];             // lane-private: no race
            }
        }
    }
    __syncthreads();

    for (int i = tid; i < NLAB * DIM; i += THREADS) {
        float s = 0.f;
        #pragma unroll
        for (int w = 0; w < NWARP; w++) s += s_sums[w][i];
        atomicAdd(&g_sums[b * NLAB * DIM + i], s);
    }
    for (int i = tid; i < NLAB; i += THREADS) {
        float s = 0.f;
        #pragma unroll
        for (int w = 0; w < NWARP; w++) s += s_cnt[w][i];
        atomicAdd(&g_counts[b * NLAB + i], s);
    }
}

// Pass 3: hinge(||x - mean[label]|| - 0.1), segment-summed per (b,label).
// REVERSED block order: reads pass1's L2-resident tail first (the load-bearing
// trick from the 64us run). float4 quartets, 8 LDG.128 staged, 3-deep shfl
// reduce, group-private hinge replicas.
__global__ void __launch_bounds__(THREADS) k_pass3(const float* __restrict__ emb,
                                                   const int* __restrict__ lab) {
    __shared__ __align__(16) float s_mean[NLAB * DIM];
    __shared__ float s_h[NWARP * 4][NLAB];
    int tid = threadIdx.x, wid = tid >> 5, lane = tid & 31;
    int g = lane >> 3, s = lane & 7;

    int idx = NBLK - 1 - blockIdx.x;                    // reversed for L2 reuse
    int b = idx / CHUNKS;
    int chunk = idx % CHUNKS;

    for (int i = tid; i < NLAB * DIM; i += THREADS) {
        float c = g_counts[b * NLAB + i / DIM];
        s_mean[i] = g_sums[b * NLAB * DIM + i] / fmaxf(c, 1.f);
    }
    for (int i = tid; i < NWARP * 4 * NLAB; i += THREADS) (&s_h[0][0])[i] = 0.f;
    __syncthreads();

    const float4* e4 = (const float4*)(emb + ((size_t)b * NPTS + (size_t)chunk * CHUNK) * DIM);
    const int*    lbase = lab + (size_t)b * NPTS + (size_t)chunk * CHUNK;
    const float4* m4 = (const float4*)s_mean;
    float* wh = s_h[wid * 4 + g];
    int p0 = wid * WPTS;

    for (int w = 0; w < WPTS; w += 32) {
        int myl = lbase[p0 + w + lane];
        float4 v[8]; int lq[8];
        #pragma unroll
        for (int q = 0; q < 8; q++) {                   // 8 LDG.128 in flight
            int p = p0 + w + q * 4 + g;
            v[q] = e4[(size_t)p * 8 + s];               // 512B/warp contiguous
            lq[q] = __shfl_sync(0xffffffffu, myl, q * 4 + g);
        }
        #pragma unroll
        for (int q = 0; q < 8; q++) {
            float4 m = m4[lq[q] * 8 + s];
            float dx = v[q].x - m.x, dy = v[q].y - m.y;
            float dz = v[q].z - m.z, dw = v[q].w - m.w;
            float sq = dx * dx + dy * dy + dz * dz + dw * dw;
            sq += __shfl_xor_sync(0xffffffffu, sq, 1);
            sq += __shfl_xor_sync(0xffffffffu, sq, 2);
            sq += __shfl_xor_sync(0xffffffffu, sq, 4);
            if (s == 0) {
                float dist = sqrtf(sq + 1e-24f);
                wh[lq[q]] += fmaxf(dist - 0.1f, 0.f);   // group-private
            }
        }
    }
    __syncthreads();

    for (int i = tid; i < NLAB; i += THREADS) {
        float acc = 0.f;
        #pragma unroll
        for (int r = 0; r < NWARP * 4; r++) acc += s_h[r][i];
        atomicAdd(&g_hinge[b * NLAB + i], acc);
    }
}

// Finalize: ONE block, warp w = batch w. Chain-free normalization; re-zeros
// accumulators at the end so the next graph replay starts clean.
__global__ void __launch_bounds__(THREADS) k_final(float* __restrict__ out) {
    __shared__ __align__(16) float s_buf[BATCH * DIM * ROWW + 16];
    int tid = threadIdx.x, wid = tid >> 5, lane = tid & 31;
    int b = wid;
    float* sm = s_buf + b * (DIM * ROWW);               // [dim][k] rows of 33
    float* s_res = s_buf + BATCH * DIM * ROWW;          // 16 floats

    float cvec = g_counts[b * NLAB + 1 + lane];         // lane <-> label lane+1
    float pres = (cvec > 0.f) ? 1.f : 0.f;
    float hs   = g_hinge[b * NLAB + 1 + lane];

    #pragma unroll
    for (int k = 0; k < KINST; k++) {
        float c = __shfl_sync(0xffffffffu, cvec, k);
        sm[lane * ROWW + k] =
            g_sums[b * NLAB * DIM + (k + 1) * DIM + lane] / fmaxf(c, 1.f);
    }
    __syncwarp();

    float nrm = 0.f;                                    // lane = instance k
    #pragma unroll
    for (int d = 0; d < DIM; d++) { float x = sm[d * ROWW + lane]; nrm += x * x; }
    float rinv = 1.f / fmaxf(sqrtf(nrm), 1e-12f);

    float mc[DIM];
    #pragma unroll
    for (int d = 0; d < DIM; d++) mc[d] = sm[d * ROWW + lane] * rinv;
    __syncwarp();
    #pragma unroll
    for (int d = 0; d < DIM; d++) sm[d * ROWW + lane] = mc[d];
    __syncwarp();

    float hp = 0.f, pm = 0.f;
    #pragma unroll 4
    for (int i = 0; i < KINST; i++) {
        float pi = __shfl_sync(0xffffffffu, pres, i);
        float mask = (lane > i) ? pi * pres : 0.f;
        float sq = 0.f;
        #pragma unroll
        for (int d = 0; d < DIM; d++) {
            float diff = sm[d * ROWW + i] - mc[d];
            sq += diff * diff;
        }
        hp += fmaxf(1.0f - sqrtf(sq + 1e-24f), 0.f) * mask;  // 2*DELTA_D = 1
        pm += mask;
    }

    float seg = hs / fmaxf(cvec, 1.f);
    float segsum = seg, ninst = pres;
    #pragma unroll
    for (int o = 16; o; o >>= 1) {
        segsum += __shfl_xor_sync(0xffffffffu, segsum, o);
        ninst  += __shfl_xor_sync(0xffffffffu, ninst, o);
        hp     += __shfl_xor_sync(0xffffffffu, hp, o);
        pm     += __shfl_xor_sync(0xffffffffu, pm, o);
    }
    if (lane == 0) {
        s_res[b * 2]     = segsum / (ninst + 1e-6f);
        s_res[b * 2 + 1] = (ninst > 1.f) ? hp / (pm + 1e-6f) : 0.f;
    }
    __syncthreads();

    if (tid < 32) {
        float pull = (lane < BATCH) ? s_res[lane * 2]     : 0.f;
        float push = (lane < BATCH) ? s_res[lane * 2 + 1] : 0.f;
        #pragma unroll
        for (int o = 4; o; o >>= 1) {
            pull += __shfl_xor_sync(0xffffffffu, pull, o);
            push += __shfl_xor_sync(0xffffffffu, push, o);
        }
        if (lane == 0) {
            pull *= (1.0f / BATCH);
            push *= (1.0f / BATCH);
            out[0] = pull + push;
            out[1] = pull;
            out[2] = push;
        }
    }
    __syncthreads();

    // re-zero accumulators for the next replay (out already written)
    for (int i = tid; i < BATCH * NLAB * DIM; i += THREADS) g_sums[i] = 0.f;
    for (int i = tid; i < BATCH * NLAB; i += THREADS) {
        g_counts[i] = 0.f;
        g_hinge[i]  = 0.f;
    }
}

extern "C" void kernel_launch(void* const* d_in, const int* in_sizes, int n_in,
                              void* d_out, int out_size) {
    const float* emb = (const float*)d_in[0];
    const int*   lab = (const int*)d_in[1];
    float* out = (float*)d_out;
    (void)in_sizes; (void)n_in; (void)out_size;

    k_pass1<<<NBLK, THREADS>>>(emb, lab);
    k_pass3<<<NBLK, THREADS>>>(emb, lab);
    k_final<<<1, THREADS>>>(out);
}

// round 9
// speedup vs baseline: 1.4109x; 1.2429x over previous
#include <cuda_runtime.h>
#include <math.h>

#define BATCH  8
#define NPTS   131072
#define DIM    32
#define NLAB   33
#define KINST  32
#define CHUNK  512
#define CHUNKS (NPTS / CHUNK)        // 256 chunks per batch
#define NBLK   (BATCH * CHUNKS)      // 2048
#define THREADS 256
#define NWARP   8
#define WPTS    (CHUNK / NWARP)      // 64 points per warp
#define ROWW   (KINST + 1)           // padded row width in finalize

// ---- scratch (no allocations allowed) ----
__device__ float g_sums[BATCH * NLAB * DIM];
__device__ float g_counts[BATCH * NLAB];
__device__ float g_hinge[BATCH * NLAB];
__device__ float g_pp[BATCH * 2];
__device__ unsigned g_fin;           // monotonic ticket (never reset)

__global__ void k_zero() {
    int i = blockIdx.x * blockDim.x + threadIdx.x;
    if (i < BATCH * NLAB * DIM) g_sums[i] = 0.f;
    if (i < BATCH * NLAB) { g_counts[i] = 0.f; g_hinge[i] = 0.f; }
}

// Pass 1: per-(b,label) sums + counts. Warp-per-point lane-private SMEM RMW
// (race-free); double-buffered 8-deep load groups (loads overlap RMW);
// labels hoisted to two coalesced loads; match_any counts.
__global__ void __launch_bounds__(THREADS) k_pass1(const float* __restrict__ emb,
                                                   const int* __restrict__ lab) {
    __shared__ float s_sums[NWARP][NLAB * DIM];
    __shared__ float s_cnt[NWARP][NLAB];
    int tid = threadIdx.x, wid = tid >> 5, lane = tid & 31;

    for (int i = tid; i < NWARP * NLAB * DIM; i += THREADS) (&s_sums[0][0])[i] = 0.f;
    for (int i = tid; i < NWARP * NLAB; i += THREADS)       (&s_cnt[0][0])[i]  = 0.f;
    __syncthreads();

    int b = blockIdx.x / CHUNKS;
    int chunk = blockIdx.x % CHUNKS;
    const float* ebase = emb + ((size_t)b * NPTS + (size_t)chunk * CHUNK) * DIM;
    const int*   lbase = lab + (size_t)b * NPTS + (size_t)chunk * CHUNK;

    float* ws = s_sums[wid];
    float* wc = s_cnt[wid];
    int p0 = wid * WPTS;

    int myl0 = lbase[p0 + lane];                    // labels for points 0..31
    int myl1 = lbase[p0 + 32 + lane];               // labels for points 32..63

    unsigned peers = __match_any_sync(0xffffffffu, myl0);
    if ((__ffs(peers) - 1) == lane) wc[myl0] += (float)__popc(peers);
    peers = __match_any_sync(0xffffffffu, myl1);
    if ((__ffs(peers) - 1) == lane) wc[myl1] += (float)__popc(peers);

    float v[8];
    #pragma unroll
    for (int i = 0; i < 8; i++)                     // prologue: group 0 in flight
        v[i] = ebase[(size_t)(p0 + i) * DIM + lane];

    #pragma unroll
    for (int gix = 0; gix < 8; gix++) {             // 8 groups of 8 points
        float vn[8];
        if (gix < 7) {
            #pragma unroll
            for (int i = 0; i < 8; i++)             // next group's loads overlap RMW
                vn[i] = ebase[(size_t)(p0 + (gix + 1) * 8 + i) * DIM + lane];
        }
        #pragma unroll
        for (int i = 0; i < 8; i++) {
            int pi = gix * 8 + i;                   // compile-time constant
            int l = (pi < 32) ? __shfl_sync(0xffffffffu, myl0, pi)
                              : __shfl_sync(0xffffffffu, myl1, pi - 32);
            ws[l * DIM + lane] += v[i];             // lane-private: no race
        }
        if (gix < 7) {
            #pragma unroll
            for (int i = 0; i < 8; i++) v[i] = vn[i];
        }
    }
    __syncthreads();

    for (int i = tid; i < NLAB * DIM; i += THREADS) {
        float s = 0.f;
        #pragma unroll
        for (int w = 0; w < NWARP; w++) s += s_sums[w][i];
        atomicAdd(&g_sums[b * NLAB * DIM + i], s);
    }
    for (int i = tid; i < NLAB; i += THREADS) {
        float s = 0.f;
        #pragma unroll
        for (int w = 0; w < NWARP; w++) s += s_cnt[w][i];
        atomicAdd(&g_counts[b * NLAB + i], s);
    }
}

// Pass 3: hinge(||x - mean[label]|| - 0.1), segment-summed per (b,label).
// REVERSED block order (L2 reuse of pass1's tail). float4 quartets,
// 8 LDG.128 staged, 3-deep shfl reduce, group-private hinge replicas.
__global__ void __launch_bounds__(THREADS) k_pass3(const float* __restrict__ emb,
                                                   const int* __restrict__ lab) {
    __shared__ __align__(16) float s_mean[NLAB * DIM];
    __shared__ float s_h[NWARP * 4][NLAB];
    int tid = threadIdx.x, wid = tid >> 5, lane = tid & 31;
    int g = lane >> 3, s = lane & 7;

    int idx = NBLK - 1 - blockIdx.x;                // reversed for L2 reuse
    int b = idx / CHUNKS;
    int chunk = idx % CHUNKS;

    for (int i = tid; i < NLAB * DIM; i += THREADS) {
        float c = g_counts[b * NLAB + i / DIM];
        s_mean[i] = g_sums[b * NLAB * DIM + i] / fmaxf(c, 1.f);
    }
    for (int i = tid; i < NWARP * 4 * NLAB; i += THREADS) (&s_h[0][0])[i] = 0.f;
    __syncthreads();

    const float4* e4 = (const float4*)(emb + ((size_t)b * NPTS + (size_t)chunk * CHUNK) * DIM);
    const int*    lbase = lab + (size_t)b * NPTS + (size_t)chunk * CHUNK;
    const float4* m4 = (const float4*)s_mean;
    float* wh = s_h[wid * 4 + g];
    int p0 = wid * WPTS;

    for (int w = 0; w < WPTS; w += 32) {
        int myl = lbase[p0 + w + lane];
        float4 v[8]; int lq[8];
        #pragma unroll
        for (int q = 0; q < 8; q++) {               // 8 LDG.128 in flight
            int p = p0 + w + q * 4 + g;
            v[q] = e4[(size_t)p * 8 + s];           // 512B/warp contiguous
            lq[q] = __shfl_sync(0xffffffffu, myl, q * 4 + g);
        }
        #pragma unroll
        for (int q = 0; q < 8; q++) {
            float4 m = m4[lq[q] * 8 + s];
            float dx = v[q].x - m.x, dy = v[q].y - m.y;
            float dz = v[q].z - m.z, dw = v[q].w - m.w;
            float sq = dx * dx + dy * dy + dz * dz + dw * dw;
            sq += __shfl_xor_sync(0xffffffffu, sq, 1);
            sq += __shfl_xor_sync(0xffffffffu, sq, 2);
            sq += __shfl_xor_sync(0xffffffffu, sq, 4);
            if (s == 0) {
                float dist = sqrtf(sq + 1e-24f);
                wh[lq[q]] += fmaxf(dist - 0.1f, 0.f);
            }
        }
    }
    __syncthreads();

    for (int i = tid; i < NLAB; i += THREADS) {
        float acc = 0.f;
        #pragma unroll
        for (int r = 0; r < NWARP * 4; r++) acc += s_h[r][i];
        atomicAdd(&g_hinge[b * NLAB + i], acc);
    }
}

// Finalize: grid=8 (one block per batch), chain-free phases; block 0 then
// reduces via the monotonic ticket barrier (all 8 blocks co-resident).
__global__ void __launch_bounds__(THREADS) k_final(float* __restrict__ out) {
    __shared__ __align__(16) float sm[DIM * ROWW];  // [dim][k], padded
    __shared__ float s_pres[KINST];
    __shared__ float s_hp[NWARP], s_pm[NWARP];
    __shared__ unsigned s_target;
    int tid = threadIdx.x, wid = tid >> 5, lane = tid & 31;
    int b = blockIdx.x;

    // Phase A: all 8 warps load means in parallel (warp w -> instances w*4..+3)
    #pragma unroll
    for (int i = 0; i < 4; i++) {
        int k = wid * 4 + i;
        float c = g_counts[b * NLAB + 1 + k];       // broadcast load
        float m = g_sums[b * NLAB * DIM + (k + 1) * DIM + lane] / fmaxf(c, 1.f);
        sm[lane * ROWW + k] = m;                    // lane = dim
        if (lane == 0) s_pres[k] = (c > 0.f) ? 1.f : 0.f;
    }
    __syncthreads();

    // Phase B: warp 0 normalizes; lane = instance k, serial over dims
    if (wid == 0) {
        float nrm = 0.f;
        #pragma unroll
        for (int d = 0; d < DIM; d++) { float x = sm[d * ROWW + lane]; nrm += x * x; }
        float rinv = 1.f / fmaxf(sqrtf(nrm), 1e-12f);
        #pragma unroll
        for (int d = 0; d < DIM; d++) sm[d * ROWW + lane] *= rinv;
    }
    __syncthreads();

    // Phase C: pair loop split over 8 warps (warp w -> i = w*4..w*4+3)
    float pres = s_pres[lane];                      // lane = j
    float mc[DIM];
    #pragma unroll
    for (int d = 0; d < DIM; d++) mc[d] = sm[d * ROWW + lane];

    float hp = 0.f, pm = 0.f;
    #pragma unroll
    for (int ii = 0; ii < 4; ii++) {
        int i = wid * 4 + ii;
        float pi = s_pres[i];
        float mask = (lane > i) ? pi * pres : 0.f;
        float sq = 0.f;
        #pragma unroll
        for (int d = 0; d < DIM; d++) {
            float diff = sm[d * ROWW + i] - mc[d];  // broadcast + register
            sq += diff * diff;
        }
        hp += fmaxf(1.0f - sqrtf(sq + 1e-24f), 0.f) * mask;  // 2*DELTA_D = 1
        pm += mask;
    }
    #pragma unroll
    for (int o = 16; o; o >>= 1) {
        hp += __shfl_xor_sync(0xffffffffu, hp, o);
        pm += __shfl_xor_sync(0xffffffffu, pm, o);
    }
    if (lane == 0) { s_hp[wid] = hp; s_pm[wid] = pm; }
    __syncthreads();

    if (wid == 0) {
        float c  = g_counts[b * NLAB + 1 + lane];
        float hs = g_hinge[b * NLAB + 1 + lane];
        float seg  = hs / fmaxf(c, 1.f);
        float pr   = (c > 0.f) ? 1.f : 0.f;
        float segsum = seg, ninst = pr;
        float hps = (lane < NWARP) ? s_hp[lane] : 0.f;
        float pms = (lane < NWARP) ? s_pm[lane] : 0.f;
        #pragma unroll
        for (int o = 16; o; o >>= 1) {
            segsum += __shfl_xor_sync(0xffffffffu, segsum, o);
            ninst  += __shfl_xor_sync(0xffffffffu, ninst, o);
            hps    += __shfl_xor_sync(0xffffffffu, hps, o);
            pms    += __shfl_xor_sync(0xffffffffu, pms, o);
        }
        if (lane == 0) {
            __stcg(&g_pp[b * 2],     segsum / (ninst + 1e-6f));
            __stcg(&g_pp[b * 2 + 1], (ninst > 1.f) ? hps / (pms + 1e-6f) : 0.f);
        }
    }

    // monotonic ticket barrier (replay-safe; 8 blocks always co-resident)
    __syncthreads();
    __threadfence();
    if (tid == 0) {
        unsigned t = atomicAdd(&g_fin, 1u);
        if (b == 0) s_target = (t / 8u + 1u) * 8u;
    }
    __syncthreads();

    if (b == 0 && tid == 0) {
        unsigned target = s_target;
        while (atomicAdd(&g_fin, 0u) < target) __nanosleep(128);
        __threadfence();
        float pull = 0.f, push = 0.f;
        #pragma unroll
        for (int bb = 0; bb < BATCH; bb++) {
            pull += __ldcg(&g_pp[bb * 2]);
            push += __ldcg(&g_pp[bb * 2 + 1]);
        }
        pull *= (1.0f / BATCH);
        push *= (1.0f / BATCH);
        out[0] = pull + push;
        out[1] = pull;
        out[2] = push;
    }
}

extern "C" void kernel_launch(void* const* d_in, const int* in_sizes, int n_in,
                              void* d_out, int out_size) {
    const float* emb = (const float*)d_in[0];
    const int*   lab = (const int*)d_in[1];
    float* out = (float*)d_out;
    (void)in_sizes; (void)n_in; (void)out_size;

    k_zero<<<(BATCH * NLAB * DIM + 255) / 256, 256>>>();
    k_pass1<<<NBLK, THREADS>>>(emb, lab);
    k_pass3<<<NBLK, THREADS>>>(emb, lab);
    k_final<<<BATCH, THREADS>>>(out);
}